// round 1
// baseline (speedup 1.0000x reference)
#include <cuda_runtime.h>
#include <math.h>

// Problem constants
#define B_ 4
#define L_ 512
#define M_ 2048
#define D_ 1024
#define H_ 8
#define K_ 128
#define W_ 2560
#define BDS 2052           // padded row stride for bd scratch (>= 2049)

// -------- scratch (device globals; no allocation allowed) --------
__device__ float g_xt[(size_t)B_ * L_ * D_];        // rmsnormed x      [2048,1024]
__device__ float g_q [(size_t)B_ * L_ * D_];        // q / tau          [2048,1024]
__device__ float g_k [(size_t)B_ * L_ * D_];
__device__ float g_v [(size_t)B_ * L_ * D_];
__device__ float g_sin[(size_t)W_ * D_];            // sinusoid table   [2560,1024]
__device__ float g_r [(size_t)W_ * D_];             // pos keys         [2560,1024]
__device__ float g_bd[(size_t)B_ * H_ * L_ * BDS];  // bd[b,h,i,d]      ~134MB
__device__ float g_wv[(size_t)B_ * L_ * D_];        // attention output [2048,1024]

// ---------------- RMSNorm ----------------
__global__ void rmsnorm_kernel(const float* __restrict__ x,
                               const float* __restrict__ g,
                               float* __restrict__ out)
{
    int row = blockIdx.x;
    int tid = threadIdx.x;
    const float4* xr = (const float4*)(x + (size_t)row * D_);
    float4 v = xr[tid];
    float ss = v.x * v.x + v.y * v.y + v.z * v.z + v.w * v.w;
    #pragma unroll
    for (int o = 16; o > 0; o >>= 1) ss += __shfl_xor_sync(0xffffffffu, ss, o);
    __shared__ float ws[8];
    if ((tid & 31) == 0) ws[tid >> 5] = ss;
    __syncthreads();
    if (tid < 8) {
        float t = ws[tid];
        #pragma unroll
        for (int o = 4; o > 0; o >>= 1) t += __shfl_xor_sync(0xffu, t, o);
        if (tid == 0) ws[0] = t;
    }
    __syncthreads();
    float scale = rsqrtf(ws[0] * (1.0f / (float)D_) + 1e-6f);
    float4 gv = ((const float4*)g)[tid];
    float4 o;
    o.x = v.x * scale * gv.x;
    o.y = v.y * scale * gv.y;
    o.z = v.z * scale * gv.z;
    o.w = v.w * scale * gv.w;
    ((float4*)(out + (size_t)row * D_))[tid] = o;
}

// ---------------- generic 64x64 fp32 GEMM (exact-tile shapes only) ----------------
// C[Md,Nd] = alpha * A[Md,Kdim] @ Bm[Kdim,Nd]   (row-major, all dims % 64 == 0 for M,N; K % 16 == 0)
__global__ void gemm64(const float* __restrict__ A, const float* __restrict__ Bm,
                       float* __restrict__ C, int Md, int Nd, int Kdim, float alpha)
{
    __shared__ float As[16][68];
    __shared__ float Bs[16][64];
    int tid = threadIdx.x;
    int row0 = blockIdx.y * 64, col0 = blockIdx.x * 64;
    int ty = tid >> 4, tx = tid & 15;
    float acc[4][4];
    #pragma unroll
    for (int i = 0; i < 4; i++)
        #pragma unroll
        for (int j = 0; j < 4; j++) acc[i][j] = 0.f;

    for (int k0 = 0; k0 < Kdim; k0 += 16) {
        #pragma unroll
        for (int l = 0; l < 4; l++) {
            int idx = tid + l * 256;
            int ra = idx >> 4, ka = idx & 15;
            As[ka][ra] = A[(size_t)(row0 + ra) * Kdim + k0 + ka];
            int kb = idx >> 6, cb = idx & 63;
            Bs[kb][cb] = Bm[(size_t)(k0 + kb) * Nd + col0 + cb];
        }
        __syncthreads();
        #pragma unroll
        for (int kk = 0; kk < 16; kk++) {
            float4 a  = *(const float4*)&As[kk][ty * 4];
            float4 bb = *(const float4*)&Bs[kk][tx * 4];
            float af[4] = {a.x, a.y, a.z, a.w};
            float bf[4] = {bb.x, bb.y, bb.z, bb.w};
            #pragma unroll
            for (int i = 0; i < 4; i++)
                #pragma unroll
                for (int j = 0; j < 4; j++) acc[i][j] += af[i] * bf[j];
        }
        __syncthreads();
    }
    #pragma unroll
    for (int i = 0; i < 4; i++) {
        size_t roff = (size_t)(row0 + ty * 4 + i) * Nd + col0 + tx * 4;
        float4 o;
        o.x = acc[i][0] * alpha; o.y = acc[i][1] * alpha;
        o.z = acc[i][2] * alpha; o.w = acc[i][3] * alpha;
        *(float4*)(C + roff) = o;
    }
}

// ---------------- sinusoid table (flipped Transformer-XL) ----------------
__global__ void sinusoid_kernel()
{
    int w = blockIdx.x;           // 0..2559
    int p = (W_ - 1) - w;         // flipped position
    for (int i = threadIdx.x; i < D_ / 2; i += blockDim.x) {
        double f = exp(-(double)i * (9.210340371976184 / 512.0)); // 10000^{-i/512}
        double ang = (double)p * f;
        g_sin[(size_t)w * D_ + i]            = (float)sin(ang);
        g_sin[(size_t)w * D_ + D_ / 2 + i]   = (float)cos(ang);
    }
}

// ---------------- bd[b,h,i,d] = (q/tau + xl_v) . R[h][511+d] ----------------
// grid (33 d-tiles, 8 i-tiles, 32 bh), 256 threads, dynamic smem 64KB
__global__ void bd_kernel(const float* __restrict__ xlv)
{
    extern __shared__ float sm[];
    float* At = sm;            // [128][64] (t-major)
    float* Rt = sm + 128 * 64; // [128][64]
    int tid = threadIdx.x;
    int d0 = blockIdx.x * 64;
    int i0 = blockIdx.y * 64;
    int bh = blockIdx.z;
    int b = bh >> 3, h = bh & 7;

    for (int e = tid; e < 64 * 32; e += 256) {
        int r = e >> 5, t4 = e & 31;
        float4 qv = *(const float4*)(g_q + ((size_t)(b * L_ + i0 + r) * D_) + h * K_ + t4 * 4);
        float4 vv = *(const float4*)(xlv + h * K_ + t4 * 4);
        int t = t4 * 4;
        At[(t + 0) * 64 + r] = qv.x + vv.x;
        At[(t + 1) * 64 + r] = qv.y + vv.y;
        At[(t + 2) * 64 + r] = qv.z + vv.z;
        At[(t + 3) * 64 + r] = qv.w + vv.w;
        int grow = 511 + d0 + r; if (grow > W_ - 1) grow = W_ - 1;
        float4 rv = *(const float4*)(g_r + (size_t)grow * D_ + h * K_ + t4 * 4);
        Rt[(t + 0) * 64 + r] = rv.x;
        Rt[(t + 1) * 64 + r] = rv.y;
        Rt[(t + 2) * 64 + r] = rv.z;
        Rt[(t + 3) * 64 + r] = rv.w;
    }
    __syncthreads();

    int ar = tid >> 4, ac = tid & 15;
    float s[4][4];
    #pragma unroll
    for (int i = 0; i < 4; i++)
        #pragma unroll
        for (int j = 0; j < 4; j++) s[i][j] = 0.f;

    #pragma unroll 4
    for (int t = 0; t < 128; t++) {
        float4 qa = *(const float4*)(At + t * 64 + ar * 4);
        float4 rb = *(const float4*)(Rt + t * 64 + ac * 4);
        float qf[4] = {qa.x, qa.y, qa.z, qa.w};
        float rf[4] = {rb.x, rb.y, rb.z, rb.w};
        #pragma unroll
        for (int i = 0; i < 4; i++)
            #pragma unroll
            for (int j = 0; j < 4; j++) s[i][j] += qf[i] * rf[j];
    }

    #pragma unroll
    for (int i = 0; i < 4; i++) {
        int gi = i0 + ar * 4 + i;
        float* bdr = g_bd + ((size_t)bh * L_ + gi) * BDS;
        #pragma unroll
        for (int j = 0; j < 4; j++) {
            int gd = d0 + ac * 4 + j;
            if (gd <= 2048) bdr[gd] = s[i][j];
        }
    }
}

// ---------------- banded flash attention ----------------
// grid (8 q-tiles, 32 bh), 256 threads, dynamic smem ~113KB
__global__ void attn_kernel(const float* __restrict__ cacheK,
                            const float* __restrict__ cacheV,
                            const float* __restrict__ xlu,
                            const int* __restrict__ posp)
{
    extern __shared__ float sm[];
    float* Qt   = sm;                 // [128][64] t-major (q/tau + u)
    float* Kt   = Qt + 128 * 64;      // [128][64]
    float* Vs   = Kt + 128 * 64;      // [64][128]
    float* Ssm  = Vs + 64 * 128;      // [64][64]
    float* mrow = Ssm + 64 * 64;      // [64]
    float* lrow = mrow + 64;          // [64]
    float* arow = lrow + 64;          // [64]

    int tid = threadIdx.x;
    int bh = blockIdx.y;
    int b = bh >> 3, h = bh & 7;
    int i0 = blockIdx.x * 64;
    int inval = M_ - posp[0]; if (inval < 0) inval = 0;

    // load Q tile (+ xl_u), transposed
    const float* qbase = g_q + ((size_t)(b * L_ + i0) * D_) + h * K_;
    for (int e = tid; e < 64 * 32; e += 256) {
        int r = e >> 5, t4 = e & 31;
        float4 qv = *(const float4*)(qbase + (size_t)r * D_ + t4 * 4);
        float4 uv = *(const float4*)(xlu + h * K_ + t4 * 4);
        int t = t4 * 4;
        Qt[(t + 0) * 64 + r] = qv.x + uv.x;
        Qt[(t + 1) * 64 + r] = qv.y + uv.y;
        Qt[(t + 2) * 64 + r] = qv.z + uv.z;
        Qt[(t + 3) * 64 + r] = qv.w + uv.w;
    }
    if (tid < 64) { mrow[tid] = -1e30f; lrow[tid] = 0.f; }

    float acc[8][4];
    #pragma unroll
    for (int i = 0; i < 8; i++)
        #pragma unroll
        for (int j = 0; j < 4; j++) acc[i][j] = 0.f;

    int tr = tid >> 5, tc = tid & 31;   // phase C: rows tr*8.., cols tc*4..
    int ar = tid >> 4, ac = tid & 15;   // phase A: rows ar*4.., cols ac*4..
    int srow = tid >> 2, sg = tid & 3;  // phase B: 4 threads per row

    __syncthreads();

    const float* bdbase = g_bd + (size_t)bh * L_ * BDS;

    for (int kt = 0; kt < 33; kt++) {
        int j0 = i0 + kt * 64;
        // load K (transposed) and V (natural)
        for (int e = tid; e < 64 * 32; e += 256) {
            int r = e >> 5, t4 = e & 31;
            int j = j0 + r;
            const float *kp, *vp;
            if (j < M_) {
                size_t off = ((size_t)bh * M_ + j) * K_ + t4 * 4;
                kp = cacheK + off; vp = cacheV + off;
            } else {
                size_t off = ((size_t)(b * L_ + (j - M_)) * D_) + h * K_ + t4 * 4;
                kp = g_k + off; vp = g_v + off;
            }
            float4 kv = *(const float4*)kp;
            int t = t4 * 4;
            Kt[(t + 0) * 64 + r] = kv.x;
            Kt[(t + 1) * 64 + r] = kv.y;
            Kt[(t + 2) * 64 + r] = kv.z;
            Kt[(t + 3) * 64 + r] = kv.w;
            *(float4*)(Vs + r * 128 + t4 * 4) = *(const float4*)vp;
        }
        __syncthreads();

        // phase A: S = (Q+u) K^T  (+ bd, mask)
        float s[4][4];
        #pragma unroll
        for (int i = 0; i < 4; i++)
            #pragma unroll
            for (int j = 0; j < 4; j++) s[i][j] = 0.f;
        #pragma unroll 4
        for (int t = 0; t < 128; t++) {
            float4 qa = *(const float4*)(Qt + t * 64 + ar * 4);
            float4 kb = *(const float4*)(Kt + t * 64 + ac * 4);
            float qf[4] = {qa.x, qa.y, qa.z, qa.w};
            float kf[4] = {kb.x, kb.y, kb.z, kb.w};
            #pragma unroll
            for (int i = 0; i < 4; i++)
                #pragma unroll
                for (int j = 0; j < 4; j++) s[i][j] += qf[i] * kf[j];
        }
        #pragma unroll
        for (int i = 0; i < 4; i++) {
            int gi = i0 + ar * 4 + i;
            const float* bdr = bdbase + (size_t)gi * BDS;
            #pragma unroll
            for (int j = 0; j < 4; j++) {
                int gj = j0 + ac * 4 + j;
                int d = gj - gi;
                float val = (d >= 0 && d <= 2048 && gj >= inval)
                          ? (s[i][j] + bdr[d]) : -1e30f;
                Ssm[(ar * 4 + i) * 64 + ac * 4 + j] = val;
            }
        }
        __syncthreads();

        // phase B: online softmax per row (4 lanes / row)
        {
            float* Sr = Ssm + srow * 64 + sg * 16;
            float mx = -1e30f;
            #pragma unroll
            for (int c = 0; c < 16; c++) mx = fmaxf(mx, Sr[c]);
            mx = fmaxf(mx, __shfl_xor_sync(0xffffffffu, mx, 1));
            mx = fmaxf(mx, __shfl_xor_sync(0xffffffffu, mx, 2));
            float mold = mrow[srow];
            float mnew = fmaxf(mold, mx);
            float sum = 0.f;
            #pragma unroll
            for (int c = 0; c < 16; c++) {
                float p = __expf(Sr[c] - mnew);
                Sr[c] = p;
                sum += p;
            }
            sum += __shfl_xor_sync(0xffffffffu, sum, 1);
            sum += __shfl_xor_sync(0xffffffffu, sum, 2);
            if (sg == 0) {
                float alpha = __expf(mold - mnew);
                arow[srow] = alpha;
                lrow[srow] = lrow[srow] * alpha + sum;
                mrow[srow] = mnew;
            }
        }
        __syncthreads();

        // phase C: rescale + O += P @ V
        #pragma unroll
        for (int i = 0; i < 8; i++) {
            float al = arow[tr * 8 + i];
            #pragma unroll
            for (int j = 0; j < 4; j++) acc[i][j] *= al;
        }
        #pragma unroll 2
        for (int k = 0; k < 64; k++) {
            float4 vv = *(const float4*)(Vs + k * 128 + tc * 4);
            #pragma unroll
            for (int i = 0; i < 8; i++) {
                float p = Ssm[(tr * 8 + i) * 64 + k];
                acc[i][0] += p * vv.x;
                acc[i][1] += p * vv.y;
                acc[i][2] += p * vv.z;
                acc[i][3] += p * vv.w;
            }
        }
        __syncthreads();
    }

    // epilogue: normalize, write wv[b, i, h*K + c]
    #pragma unroll
    for (int i = 0; i < 8; i++) {
        int r = tr * 8 + i;
        float inv = 1.0f / lrow[r];
        float4 o;
        o.x = acc[i][0] * inv; o.y = acc[i][1] * inv;
        o.z = acc[i][2] * inv; o.w = acc[i][3] * inv;
        *(float4*)(g_wv + ((size_t)(b * L_ + i0 + r) * D_) + h * K_ + tc * 4) = o;
    }
}

// ---------------- launch ----------------
extern "C" void kernel_launch(void* const* d_in, const int* in_sizes, int n_in,
                              void* d_out, int out_size)
{
    const float* x        = (const float*)d_in[0];
    const int*   pos      = (const int*)  d_in[1];
    const float* cacheK   = (const float*)d_in[2];
    const float* cacheV   = (const float*)d_in[3];
    const float* g_rms    = (const float*)d_in[4];
    const float* Wq       = (const float*)d_in[5];
    const float* Wk       = (const float*)d_in[6];
    const float* Wv       = (const float*)d_in[7];
    const float* Wr       = (const float*)d_in[8];
    const float* xlu      = (const float*)d_in[9];
    const float* xlv      = (const float*)d_in[10];
    const float* Wo       = (const float*)d_in[11];
    float* out            = (float*)d_out;

    float *p_xt, *p_q, *p_k, *p_v, *p_sin, *p_r, *p_wv;
    cudaGetSymbolAddress((void**)&p_xt,  g_xt);
    cudaGetSymbolAddress((void**)&p_q,   g_q);
    cudaGetSymbolAddress((void**)&p_k,   g_k);
    cudaGetSymbolAddress((void**)&p_v,   g_v);
    cudaGetSymbolAddress((void**)&p_sin, g_sin);
    cudaGetSymbolAddress((void**)&p_r,   g_r);
    cudaGetSymbolAddress((void**)&p_wv,  g_wv);

    const int ATT_SMEM = (128 * 64 * 2 + 64 * 128 + 64 * 64 + 3 * 64) * 4; // 115456
    const int BD_SMEM  = 2 * 128 * 64 * 4;                                  // 65536
    cudaFuncSetAttribute(attn_kernel, cudaFuncAttributeMaxDynamicSharedMemorySize, ATT_SMEM);
    cudaFuncSetAttribute(bd_kernel,   cudaFuncAttributeMaxDynamicSharedMemorySize, BD_SMEM);

    const float inv_tau = 0.08838834764831845f; // 1/sqrt(128)

    // 1) RMSNorm
    rmsnorm_kernel<<<B_ * L_, 256>>>(x, g_rms, p_xt);

    // 2) Q/K/V projections
    gemm64<<<dim3(D_ / 64, (B_ * L_) / 64), 256>>>(p_xt, Wq, p_q, B_ * L_, D_, D_, inv_tau);
    gemm64<<<dim3(D_ / 64, (B_ * L_) / 64), 256>>>(p_xt, Wk, p_k, B_ * L_, D_, D_, 1.0f);
    gemm64<<<dim3(D_ / 64, (B_ * L_) / 64), 256>>>(p_xt, Wv, p_v, B_ * L_, D_, D_, 1.0f);

    // 3) positional keys R = sinusoid @ Wr
    sinusoid_kernel<<<W_, 128>>>();
    gemm64<<<dim3(D_ / 64, W_ / 64), 256>>>(p_sin, Wr, p_r, W_, D_, D_, 1.0f);

    // 4) bd scores
    bd_kernel<<<dim3(33, L_ / 64, B_ * H_), 256, BD_SMEM>>>(xlv);

    // 5) banded flash attention
    attn_kernel<<<dim3(L_ / 64, B_ * H_), 256, ATT_SMEM>>>(cacheK, cacheV, xlu, pos);

    // 6) output projection
    gemm64<<<dim3(D_ / 64, (B_ * L_) / 64), 256>>>(p_wv, Wo, out, B_ * L_, D_, D_, 1.0f);
}

// round 2
// speedup vs baseline: 1.9031x; 1.9031x over previous
#include <cuda_runtime.h>
#include <math.h>

// Problem constants
#define B_ 4
#define L_ 512
#define M_ 2048
#define D_ 1024
#define H_ 8
#define K_ 128
#define W_ 2560
#define BDS 2052           // padded row stride for bd scratch (>= 2049)

// -------- scratch (device globals; no allocation allowed) --------
__device__ float g_xt[(size_t)B_ * L_ * D_];        // rmsnormed x      [2048,1024]
__device__ float g_q [(size_t)B_ * L_ * D_];        // q / tau          [2048,1024]
__device__ float g_k [(size_t)B_ * L_ * D_];
__device__ float g_v [(size_t)B_ * L_ * D_];
__device__ float g_sin[(size_t)W_ * D_];            // sinusoid table   [2560,1024]
__device__ float g_r [(size_t)W_ * D_];             // pos keys         [2560,1024]
__device__ float g_bd[(size_t)B_ * H_ * L_ * BDS];  // bd[b,h,i,d]      ~134MB
__device__ float g_wv[(size_t)B_ * L_ * D_];        // attention output [2048,1024]

// ---------------- mma helpers ----------------
__device__ __forceinline__ unsigned tf32cvt(float f) {
    unsigned r;
    asm("cvt.rna.tf32.f32 %0, %1;" : "=r"(r) : "f"(f));
    return r;
}

__device__ __forceinline__ void mma8(float* c, const unsigned* a, const unsigned* b) {
    asm("mma.sync.aligned.m16n8k8.row.col.f32.tf32.tf32.f32 "
        "{%0,%1,%2,%3},{%4,%5,%6,%7},{%8,%9},{%0,%1,%2,%3};"
        : "+f"(c[0]), "+f"(c[1]), "+f"(c[2]), "+f"(c[3])
        : "r"(a[0]), "r"(a[1]), "r"(a[2]), "r"(a[3]), "r"(b[0]), "r"(b[1]));
}

// ---------------- RMSNorm ----------------
__global__ void rmsnorm_kernel(const float* __restrict__ x,
                               const float* __restrict__ g,
                               float* __restrict__ out)
{
    int row = blockIdx.x;
    int tid = threadIdx.x;
    const float4* xr = (const float4*)(x + (size_t)row * D_);
    float4 v = xr[tid];
    float ss = v.x * v.x + v.y * v.y + v.z * v.z + v.w * v.w;
    #pragma unroll
    for (int o = 16; o > 0; o >>= 1) ss += __shfl_xor_sync(0xffffffffu, ss, o);
    __shared__ float ws[8];
    if ((tid & 31) == 0) ws[tid >> 5] = ss;
    __syncthreads();
    if (tid < 8) {
        float t = ws[tid];
        #pragma unroll
        for (int o = 4; o > 0; o >>= 1) t += __shfl_xor_sync(0xffu, t, o);
        if (tid == 0) ws[0] = t;
    }
    __syncthreads();
    float scale = rsqrtf(ws[0] * (1.0f / (float)D_) + 1e-6f);
    float4 gv = ((const float4*)g)[tid];
    float4 o;
    o.x = v.x * scale * gv.x;
    o.y = v.y * scale * gv.y;
    o.z = v.z * scale * gv.z;
    o.w = v.w * scale * gv.w;
    ((float4*)(out + (size_t)row * D_))[tid] = o;
}

// ---------------- sinusoid table (flipped Transformer-XL) ----------------
__global__ void sinusoid_kernel()
{
    int w = blockIdx.x;           // 0..2559
    int p = (W_ - 1) - w;         // flipped position
    for (int i = threadIdx.x; i < D_ / 2; i += blockDim.x) {
        double f = exp(-(double)i * (9.210340371976184 / 512.0)); // 10000^{-i/512}
        double ang = (double)p * f;
        g_sin[(size_t)w * D_ + i]            = (float)sin(ang);
        g_sin[(size_t)w * D_ + D_ / 2 + i]   = (float)cos(ang);
    }
}

// ---------------- generic 128x128 tf32 mma GEMM (NN), dims % 128 == 0, K % 16 == 0 ----------------
__global__ void gemm_mma(const float* __restrict__ A, const float* __restrict__ Bm,
                         float* __restrict__ C, int Md, int Nd, int Kd, float alpha)
{
    __shared__ unsigned As[128][20];
    __shared__ unsigned Bs[16][136];
    int tid = threadIdx.x;
    int lane = tid & 31, wid = tid >> 5;
    int wr = wid >> 1, wc = wid & 1;
    int qr = lane >> 2, qc = lane & 3;
    int m0 = blockIdx.y * 128, n0 = blockIdx.x * 128;

    float c[2][8][4];
    #pragma unroll
    for (int i = 0; i < 2; i++)
        #pragma unroll
        for (int j = 0; j < 8; j++)
            #pragma unroll
            for (int l = 0; l < 4; l++) c[i][j][l] = 0.f;

    for (int k0 = 0; k0 < Kd; k0 += 16) {
        #pragma unroll
        for (int l = 0; l < 2; l++) {
            int idx = tid + l * 256;
            int m = idx >> 2, kq = (idx & 3) << 2;
            float4 v = *(const float4*)(A + (size_t)(m0 + m) * Kd + k0 + kq);
            uint4 u = make_uint4(tf32cvt(v.x), tf32cvt(v.y), tf32cvt(v.z), tf32cvt(v.w));
            *(uint4*)&As[m][kq] = u;

            int kb = idx >> 5, nq = (idx & 31) << 2;
            float4 w = *(const float4*)(Bm + (size_t)(k0 + kb) * Nd + n0 + nq);
            uint4 uw = make_uint4(tf32cvt(w.x), tf32cvt(w.y), tf32cvt(w.z), tf32cvt(w.w));
            *(uint4*)&Bs[kb][nq] = uw;
        }
        __syncthreads();
        #pragma unroll
        for (int ks = 0; ks < 2; ks++) {
            const int kk = ks * 8;
            unsigned a[2][4], bf[8][2];
            #pragma unroll
            for (int mt = 0; mt < 2; mt++) {
                int r = wr * 32 + mt * 16 + qr;
                a[mt][0] = As[r][kk + qc];
                a[mt][1] = As[r + 8][kk + qc];
                a[mt][2] = As[r][kk + qc + 4];
                a[mt][3] = As[r + 8][kk + qc + 4];
            }
            #pragma unroll
            for (int nt = 0; nt < 8; nt++) {
                int cn = wc * 64 + nt * 8 + qr;
                bf[nt][0] = Bs[kk + qc][cn];
                bf[nt][1] = Bs[kk + qc + 4][cn];
            }
            #pragma unroll
            for (int mt = 0; mt < 2; mt++)
                #pragma unroll
                for (int nt = 0; nt < 8; nt++)
                    mma8(c[mt][nt], a[mt], bf[nt]);
        }
        __syncthreads();
    }

    #pragma unroll
    for (int mt = 0; mt < 2; mt++) {
        int r = m0 + wr * 32 + mt * 16 + qr;
        #pragma unroll
        for (int nt = 0; nt < 8; nt++) {
            int col = n0 + wc * 64 + nt * 8 + qc * 2;
            float2 v0 = make_float2(c[mt][nt][0] * alpha, c[mt][nt][1] * alpha);
            float2 v1 = make_float2(c[mt][nt][2] * alpha, c[mt][nt][3] * alpha);
            *(float2*)(C + (size_t)r * Nd + col) = v0;
            *(float2*)(C + (size_t)(r + 8) * Nd + col) = v1;
        }
    }
}

// ---------------- bd GEMM:  bd[bh][i][d] = (q[bh][i] + xlv[h]) . g_r[h][511+d] ----------------
// grid (17 d-tiles, 4 i-tiles, 32 bh), 256 threads
__global__ void bd_mma(const float* __restrict__ xlv)
{
    __shared__ unsigned As[128][20];
    __shared__ unsigned Bs[16][136];
    int tid = threadIdx.x;
    int lane = tid & 31, wid = tid >> 5;
    int wr = wid >> 1, wc = wid & 1;
    int qr = lane >> 2, qc = lane & 3;
    int d0 = blockIdx.x * 128;
    int i0 = blockIdx.y * 128;
    int bh = blockIdx.z;
    int b = bh >> 3, h = bh & 7;

    float c[2][8][4];
    #pragma unroll
    for (int i = 0; i < 2; i++)
        #pragma unroll
        for (int j = 0; j < 8; j++)
            #pragma unroll
            for (int l = 0; l < 4; l++) c[i][j][l] = 0.f;

    for (int k0 = 0; k0 < K_; k0 += 16) {
        #pragma unroll
        for (int l = 0; l < 2; l++) {
            int idx = tid + l * 256;
            int m = idx >> 2, kq = (idx & 3) << 2;
            float4 v = *(const float4*)(g_q + (size_t)(b * L_ + i0 + m) * D_ + h * K_ + k0 + kq);
            float4 vv = *(const float4*)(xlv + h * K_ + k0 + kq);
            uint4 u = make_uint4(tf32cvt(v.x + vv.x), tf32cvt(v.y + vv.y),
                                 tf32cvt(v.z + vv.z), tf32cvt(v.w + vv.w));
            *(uint4*)&As[m][kq] = u;

            int n = idx >> 2;   // same mapping, n 0..127
            int rr = 511 + d0 + n; if (rr > W_ - 1) rr = W_ - 1;
            float4 rv = *(const float4*)(g_r + (size_t)rr * D_ + h * K_ + k0 + kq);
            Bs[kq + 0][n] = tf32cvt(rv.x);
            Bs[kq + 1][n] = tf32cvt(rv.y);
            Bs[kq + 2][n] = tf32cvt(rv.z);
            Bs[kq + 3][n] = tf32cvt(rv.w);
        }
        __syncthreads();
        #pragma unroll
        for (int ks = 0; ks < 2; ks++) {
            const int kk = ks * 8;
            unsigned a[2][4], bf[8][2];
            #pragma unroll
            for (int mt = 0; mt < 2; mt++) {
                int r = wr * 32 + mt * 16 + qr;
                a[mt][0] = As[r][kk + qc];
                a[mt][1] = As[r + 8][kk + qc];
                a[mt][2] = As[r][kk + qc + 4];
                a[mt][3] = As[r + 8][kk + qc + 4];
            }
            #pragma unroll
            for (int nt = 0; nt < 8; nt++) {
                int cn = wc * 64 + nt * 8 + qr;
                bf[nt][0] = Bs[kk + qc][cn];
                bf[nt][1] = Bs[kk + qc + 4][cn];
            }
            #pragma unroll
            for (int mt = 0; mt < 2; mt++)
                #pragma unroll
                for (int nt = 0; nt < 8; nt++)
                    mma8(c[mt][nt], a[mt], bf[nt]);
        }
        __syncthreads();
    }

    #pragma unroll
    for (int mt = 0; mt < 2; mt++) {
        int gi = i0 + wr * 32 + mt * 16 + qr;
        float* row0 = g_bd + ((size_t)bh * L_ + gi) * BDS;
        float* row1 = g_bd + ((size_t)bh * L_ + gi + 8) * BDS;
        #pragma unroll
        for (int nt = 0; nt < 8; nt++) {
            int gd = d0 + wc * 64 + nt * 8 + qc * 2;
            if (gd <= 2048)     { row0[gd] = c[mt][nt][0];     row1[gd] = c[mt][nt][2]; }
            if (gd + 1 <= 2048) { row0[gd + 1] = c[mt][nt][1]; row1[gd + 1] = c[mt][nt][3]; }
        }
    }
}

// ---------------- banded flash attention with mma ----------------
// grid (8 q-tiles, 32 bh), 256 threads
__global__ void attn_mma(const float* __restrict__ cacheK,
                         const float* __restrict__ cacheV,
                         const float* __restrict__ xlu,
                         const int* __restrict__ posp)
{
    extern __shared__ unsigned smu[];
    unsigned* Qs = smu;                        // [64][132]
    unsigned* Ks = Qs + 64 * 132;              // [64][132]
    unsigned* Vs = Ks + 64 * 132;              // [64][136]
    float* Ssm   = (float*)(Vs + 64 * 136);    // [64][68]
    float* mrow  = Ssm + 64 * 68;              // [64]
    float* lrow  = mrow + 64;
    float* arow  = lrow + 64;

    int tid = threadIdx.x;
    int lane = tid & 31, wid = tid >> 5;
    int wr = wid >> 1, wc = wid & 1;
    int qr = lane >> 2, qc = lane & 3;
    int bh = blockIdx.y;
    int b = bh >> 3, h = bh & 7;
    int i0 = blockIdx.x * 64;
    int inval = M_ - posp[0]; if (inval < 0) inval = 0;

    // load Q tile (+ xl_u), tf32
    const float* qbase = g_q + ((size_t)(b * L_ + i0) * D_) + h * K_;
    #pragma unroll
    for (int l = 0; l < 8; l++) {
        int idx = tid + l * 256;
        int r = idx >> 5, kq = (idx & 31) << 2;
        float4 qv = *(const float4*)(qbase + (size_t)r * D_ + kq);
        float4 uv = *(const float4*)(xlu + h * K_ + kq);
        uint4 u = make_uint4(tf32cvt(qv.x + uv.x), tf32cvt(qv.y + uv.y),
                             tf32cvt(qv.z + uv.z), tf32cvt(qv.w + uv.w));
        *(uint4*)&Qs[r * 132 + kq] = u;
    }
    if (tid < 64) { mrow[tid] = -1e30f; lrow[tid] = 0.f; }

    float oacc[8][4];
    #pragma unroll
    for (int i = 0; i < 8; i++)
        #pragma unroll
        for (int j = 0; j < 4; j++) oacc[i][j] = 0.f;

    int srow = tid >> 2, sg = tid & 3;  // softmax: 4 threads per row

    __syncthreads();

    const float* bdbase = g_bd + (size_t)bh * L_ * BDS;

    for (int kt = 0; kt < 33; kt++) {
        int j0 = i0 + kt * 64;
        // load K, V (tf32)
        #pragma unroll
        for (int l = 0; l < 8; l++) {
            int idx = tid + l * 256;
            int r = idx >> 5, kq = (idx & 31) << 2;
            int j = j0 + r;
            const float *kp, *vp;
            if (j < M_) {
                size_t off = ((size_t)bh * M_ + j) * K_ + kq;
                kp = cacheK + off; vp = cacheV + off;
            } else {
                size_t off = ((size_t)(b * L_ + (j - M_)) * D_) + h * K_ + kq;
                kp = g_k + off; vp = g_v + off;
            }
            float4 kv = *(const float4*)kp;
            float4 vv = *(const float4*)vp;
            *(uint4*)&Ks[r * 132 + kq] = make_uint4(tf32cvt(kv.x), tf32cvt(kv.y), tf32cvt(kv.z), tf32cvt(kv.w));
            *(uint4*)&Vs[r * 136 + kq] = make_uint4(tf32cvt(vv.x), tf32cvt(vv.y), tf32cvt(vv.z), tf32cvt(vv.w));
        }
        __syncthreads();

        // phase A: S = (Q+u) K^T via mma, warp tile 16x32
        float s[4][4];
        #pragma unroll
        for (int i = 0; i < 4; i++)
            #pragma unroll
            for (int j = 0; j < 4; j++) s[i][j] = 0.f;
        #pragma unroll
        for (int ks = 0; ks < 16; ks++) {
            const int kk = ks * 8;
            unsigned a[4], bf[4][2];
            int r = wr * 16 + qr;
            a[0] = Qs[r * 132 + kk + qc];
            a[1] = Qs[(r + 8) * 132 + kk + qc];
            a[2] = Qs[r * 132 + kk + qc + 4];
            a[3] = Qs[(r + 8) * 132 + kk + qc + 4];
            #pragma unroll
            for (int nt = 0; nt < 4; nt++) {
                int n = wc * 32 + nt * 8 + qr;
                bf[nt][0] = Ks[n * 132 + kk + qc];
                bf[nt][1] = Ks[n * 132 + kk + qc + 4];
            }
            #pragma unroll
            for (int nt = 0; nt < 4; nt++) mma8(s[nt], a, bf[nt]);
        }
        // write S + bd + mask into Ssm
        {
            int r = wr * 16 + qr;
            int gi0 = i0 + r, gi1 = gi0 + 8;
            const float* bdr0 = bdbase + (size_t)gi0 * BDS;
            const float* bdr1 = bdbase + (size_t)gi1 * BDS;
            #pragma unroll
            for (int nt = 0; nt < 4; nt++) {
                int cbase = wc * 32 + nt * 8 + qc * 2;
                #pragma unroll
                for (int e = 0; e < 2; e++) {
                    int cc = cbase + e;
                    int gj = j0 + cc;
                    int dd0 = gj - gi0, dd1 = gj - gi1;
                    float v0 = (dd0 >= 0 && dd0 <= 2048 && gj >= inval) ? (s[nt][e] + bdr0[dd0]) : -1e30f;
                    float v1 = (dd1 >= 0 && dd1 <= 2048 && gj >= inval) ? (s[nt][2 + e] + bdr1[dd1]) : -1e30f;
                    Ssm[r * 68 + cc] = v0;
                    Ssm[(r + 8) * 68 + cc] = v1;
                }
            }
        }
        __syncthreads();

        // phase B: online softmax per row (4 lanes / row); store P as tf32 bits
        {
            float* Sr = Ssm + srow * 68 + sg * 16;
            float mx = -1e30f;
            #pragma unroll
            for (int c2 = 0; c2 < 16; c2++) mx = fmaxf(mx, Sr[c2]);
            mx = fmaxf(mx, __shfl_xor_sync(0xffffffffu, mx, 1));
            mx = fmaxf(mx, __shfl_xor_sync(0xffffffffu, mx, 2));
            float mold = mrow[srow];
            float mnew = fmaxf(mold, mx);
            float sum = 0.f;
            #pragma unroll
            for (int c2 = 0; c2 < 16; c2++) {
                float p = __expf(Sr[c2] - mnew);
                ((unsigned*)Sr)[c2] = tf32cvt(p);
                sum += p;
            }
            sum += __shfl_xor_sync(0xffffffffu, sum, 1);
            sum += __shfl_xor_sync(0xffffffffu, sum, 2);
            if (sg == 0) {
                float alpha = __expf(mold - mnew);
                arow[srow] = alpha;
                lrow[srow] = lrow[srow] * alpha + sum;
                mrow[srow] = mnew;
            }
        }
        __syncthreads();

        // phase C: rescale + O += P @ V via mma, warp tile 16x64
        {
            int r = wr * 16 + qr;
            float al0 = arow[r], al1 = arow[r + 8];
            #pragma unroll
            for (int nt = 0; nt < 8; nt++) {
                oacc[nt][0] *= al0; oacc[nt][1] *= al0;
                oacc[nt][2] *= al1; oacc[nt][3] *= al1;
            }
            const unsigned* Pu = (const unsigned*)Ssm;
            #pragma unroll
            for (int ks = 0; ks < 8; ks++) {
                const int kk = ks * 8;
                unsigned a[4], bf[8][2];
                a[0] = Pu[r * 68 + kk + qc];
                a[1] = Pu[(r + 8) * 68 + kk + qc];
                a[2] = Pu[r * 68 + kk + qc + 4];
                a[3] = Pu[(r + 8) * 68 + kk + qc + 4];
                #pragma unroll
                for (int nt = 0; nt < 8; nt++) {
                    int n = wc * 64 + nt * 8 + qr;
                    bf[nt][0] = Vs[(kk + qc) * 136 + n];
                    bf[nt][1] = Vs[(kk + qc + 4) * 136 + n];
                }
                #pragma unroll
                for (int nt = 0; nt < 8; nt++) mma8(oacc[nt], a, bf[nt]);
            }
        }
        __syncthreads();
    }

    // epilogue: normalize, write wv
    {
        int r = wr * 16 + qr;
        float inv0 = 1.0f / lrow[r];
        float inv1 = 1.0f / lrow[r + 8];
        float* o0 = g_wv + ((size_t)(b * L_ + i0 + r) * D_) + h * K_;
        float* o1 = g_wv + ((size_t)(b * L_ + i0 + r + 8) * D_) + h * K_;
        #pragma unroll
        for (int nt = 0; nt < 8; nt++) {
            int col = wc * 64 + nt * 8 + qc * 2;
            *(float2*)(o0 + col) = make_float2(oacc[nt][0] * inv0, oacc[nt][1] * inv0);
            *(float2*)(o1 + col) = make_float2(oacc[nt][2] * inv1, oacc[nt][3] * inv1);
        }
    }
}

// ---------------- launch ----------------
extern "C" void kernel_launch(void* const* d_in, const int* in_sizes, int n_in,
                              void* d_out, int out_size)
{
    const float* x        = (const float*)d_in[0];
    const int*   pos      = (const int*)  d_in[1];
    const float* cacheK   = (const float*)d_in[2];
    const float* cacheV   = (const float*)d_in[3];
    const float* g_rms    = (const float*)d_in[4];
    const float* Wq       = (const float*)d_in[5];
    const float* Wk       = (const float*)d_in[6];
    const float* Wv       = (const float*)d_in[7];
    const float* Wr       = (const float*)d_in[8];
    const float* xlu      = (const float*)d_in[9];
    const float* xlv      = (const float*)d_in[10];
    const float* Wo       = (const float*)d_in[11];
    float* out            = (float*)d_out;

    float *p_xt, *p_q, *p_k, *p_v, *p_sin, *p_r, *p_wv;
    cudaGetSymbolAddress((void**)&p_xt,  g_xt);
    cudaGetSymbolAddress((void**)&p_q,   g_q);
    cudaGetSymbolAddress((void**)&p_k,   g_k);
    cudaGetSymbolAddress((void**)&p_v,   g_v);
    cudaGetSymbolAddress((void**)&p_sin, g_sin);
    cudaGetSymbolAddress((void**)&p_r,   g_r);
    cudaGetSymbolAddress((void**)&p_wv,  g_wv);

    const int ATT_SMEM = (64 * 132 * 2 + 64 * 136 + 64 * 68 + 3 * 64) * 4; // 120576
    cudaFuncSetAttribute(attn_mma, cudaFuncAttributeMaxDynamicSharedMemorySize, ATT_SMEM);

    const float inv_tau = 0.08838834764831845f; // 1/sqrt(128)

    // 1) RMSNorm
    rmsnorm_kernel<<<B_ * L_, 256>>>(x, g_rms, p_xt);

    // 2) Q/K/V projections (tensor cores, tf32)
    gemm_mma<<<dim3(D_ / 128, (B_ * L_) / 128), 256>>>(p_xt, Wq, p_q, B_ * L_, D_, D_, inv_tau);
    gemm_mma<<<dim3(D_ / 128, (B_ * L_) / 128), 256>>>(p_xt, Wk, p_k, B_ * L_, D_, D_, 1.0f);
    gemm_mma<<<dim3(D_ / 128, (B_ * L_) / 128), 256>>>(p_xt, Wv, p_v, B_ * L_, D_, D_, 1.0f);

    // 3) positional keys R = sinusoid @ Wr
    sinusoid_kernel<<<W_, 128>>>();
    gemm_mma<<<dim3(D_ / 128, W_ / 128), 256>>>(p_sin, Wr, p_r, W_, D_, D_, 1.0f);

    // 4) bd scores (tensor cores)
    bd_mma<<<dim3(17, L_ / 128, B_ * H_), 256>>>(xlv);

    // 5) banded flash attention (tensor cores)
    attn_mma<<<dim3(L_ / 64, B_ * H_), 256, ATT_SMEM>>>(cacheK, cacheV, xlu, pos);

    // 6) output projection
    gemm_mma<<<dim3(D_ / 128, (B_ * L_) / 128), 256>>>(p_wv, Wo, out, B_ * L_, D_, D_, 1.0f);
}

// round 3
// speedup vs baseline: 4.2109x; 2.2126x over previous
#include <cuda_runtime.h>
#include <math.h>

// Problem constants
#define B_ 4
#define L_ 512
#define M_ 2048
#define D_ 1024
#define H_ 8
#define K_ 128
#define W_ 2560

// -------- scratch (device globals; no allocation allowed) --------
__device__ float g_xt[(size_t)B_ * L_ * D_];
__device__ float g_q [(size_t)B_ * L_ * D_];
__device__ float g_k [(size_t)B_ * L_ * D_];
__device__ float g_v [(size_t)B_ * L_ * D_];
__device__ float g_sin[(size_t)W_ * D_];
__device__ float g_r [(size_t)W_ * D_];
__device__ float g_bd[(size_t)B_ * H_ * L_ * W_];   // bd[b,h,i,j] absolute-key layout, ~168MB
__device__ float g_wv[(size_t)B_ * L_ * D_];

// ---------------- helpers ----------------
__device__ __forceinline__ unsigned tf32cvt(float f) {
    unsigned r;
    asm("cvt.rna.tf32.f32 %0, %1;" : "=r"(r) : "f"(f));
    return r;
}
__device__ __forceinline__ void mma8(float* c, const unsigned* a, const unsigned* b) {
    asm("mma.sync.aligned.m16n8k8.row.col.f32.tf32.tf32.f32 "
        "{%0,%1,%2,%3},{%4,%5,%6,%7},{%8,%9},{%0,%1,%2,%3};"
        : "+f"(c[0]), "+f"(c[1]), "+f"(c[2]), "+f"(c[3])
        : "r"(a[0]), "r"(a[1]), "r"(a[2]), "r"(a[3]), "r"(b[0]), "r"(b[1]));
}
__device__ __forceinline__ void cp16(unsigned dst, const void* src) {
    asm volatile("cp.async.cg.shared.global [%0], [%1], 16;" :: "r"(dst), "l"(src));
}
__device__ __forceinline__ void cp_commit() { asm volatile("cp.async.commit_group;"); }
__device__ __forceinline__ void cp_wait1()  { asm volatile("cp.async.wait_group 1;"); }
__device__ __forceinline__ void cp_wait0()  { asm volatile("cp.async.wait_group 0;"); }
__device__ __forceinline__ unsigned saddr(const void* p) {
    return (unsigned)__cvta_generic_to_shared(p);
}

// ---------------- RMSNorm ----------------
__global__ void rmsnorm_kernel(const float* __restrict__ x,
                               const float* __restrict__ g,
                               float* __restrict__ out)
{
    int row = blockIdx.x;
    int tid = threadIdx.x;
    const float4* xr = (const float4*)(x + (size_t)row * D_);
    float4 v = xr[tid];
    float ss = v.x * v.x + v.y * v.y + v.z * v.z + v.w * v.w;
    #pragma unroll
    for (int o = 16; o > 0; o >>= 1) ss += __shfl_xor_sync(0xffffffffu, ss, o);
    __shared__ float ws[8];
    if ((tid & 31) == 0) ws[tid >> 5] = ss;
    __syncthreads();
    if (tid < 8) {
        float t = ws[tid];
        #pragma unroll
        for (int o = 4; o > 0; o >>= 1) t += __shfl_xor_sync(0xffu, t, o);
        if (tid == 0) ws[0] = t;
    }
    __syncthreads();
    float scale = rsqrtf(ws[0] * (1.0f / (float)D_) + 1e-6f);
    float4 gv = ((const float4*)g)[tid];
    float4 o;
    o.x = v.x * scale * gv.x;
    o.y = v.y * scale * gv.y;
    o.z = v.z * scale * gv.z;
    o.w = v.w * scale * gv.w;
    ((float4*)(out + (size_t)row * D_))[tid] = o;
}

// ---------------- sinusoid table (double arg + float trig) ----------------
__global__ void sinusoid_kernel()
{
    __shared__ double fd[512];
    int tid = threadIdx.x;
    int w0 = blockIdx.x * 64;
    for (int i = tid; i < 512; i += 256)
        fd[i] = exp(-(double)i * (9.210340371976184 / 512.0));
    __syncthreads();
    for (int e = tid; e < 64 * 512; e += 256) {
        int w = w0 + (e >> 9);
        int i = e & 511;
        int p = (W_ - 1) - w;
        double ang = (double)p * fd[i];
        double t = ang * 0.15915494309189535;
        t -= floor(t);
        float th = (float)(t * 6.283185307179586);
        float s, c;
        sincosf(th, &s, &c);
        g_sin[(size_t)w * D_ + i]          = s;
        g_sin[(size_t)w * D_ + 512 + i]    = c;
    }
}

// ---------------- pipelined 128x128 tf32 GEMM (NN), BK=32 ----------------
// grid (Nd/128, Mrows/128, nz); z selects (B, C, alpha)
#define GEMM_SMEM ((2 * 128 * 36 + 2 * 32 * 132) * 4)
__global__ void __launch_bounds__(256) gemm_nn(
    const float* __restrict__ A,
    const float* __restrict__ B0, const float* __restrict__ B1, const float* __restrict__ B2,
    float* __restrict__ C0, float* __restrict__ C1, float* __restrict__ C2,
    int Nd, int Kd, float a0, float a1, float a2)
{
    const float* Bm; float* C; float alpha;
    if (blockIdx.z == 0)      { Bm = B0; C = C0; alpha = a0; }
    else if (blockIdx.z == 1) { Bm = B1; C = C1; alpha = a1; }
    else                      { Bm = B2; C = C2; alpha = a2; }

    extern __shared__ float smf[];
    float* sA = smf;                    // 2 x [128][36]
    float* sB = smf + 2 * 128 * 36;     // 2 x [32][132]
    unsigned sAa = saddr(sA), sBa = saddr(sB);

    int tid = threadIdx.x;
    int lane = tid & 31, wid = tid >> 5;
    int wr = wid >> 1, wc = wid & 1;
    int qr = lane >> 2, qc = lane & 3;
    int m0 = blockIdx.y * 128, n0 = blockIdx.x * 128;
    int NIT = Kd >> 5;

    float acc[2][8][4];
    #pragma unroll
    for (int i = 0; i < 2; i++)
        #pragma unroll
        for (int j = 0; j < 8; j++)
            #pragma unroll
            for (int l = 0; l < 4; l++) acc[i][j][l] = 0.f;

    auto load_tiles = [&](int st, int k0) {
        unsigned da = sAa + st * (128 * 36 * 4);
        unsigned db = sBa + st * (32 * 132 * 4);
        #pragma unroll
        for (int j = 0; j < 4; j++) {
            int id = tid + j * 256;
            int ra = id >> 3, ca = (id & 7) << 2;
            cp16(da + (ra * 36 + ca) * 4, A + (size_t)(m0 + ra) * Kd + k0 + ca);
            int rb = id >> 5, cb = (id & 31) << 2;
            cp16(db + (rb * 132 + cb) * 4, Bm + (size_t)(k0 + rb) * Nd + n0 + cb);
        }
    };

    load_tiles(0, 0); cp_commit();

    for (int it = 0; it < NIT; it++) {
        int st = it & 1;
        if (it + 1 < NIT) { load_tiles(st ^ 1, (it + 1) << 5); cp_commit(); cp_wait1(); }
        else cp_wait0();
        __syncthreads();
        const float* cA = sA + st * (128 * 36);
        const float* cB = sB + st * (32 * 132);
        #pragma unroll
        for (int ks = 0; ks < 4; ks++) {
            const int kk = ks * 8;
            unsigned a[2][4], bf[8][2];
            #pragma unroll
            for (int mt = 0; mt < 2; mt++) {
                int r = wr * 32 + mt * 16 + qr;
                a[mt][0] = tf32cvt(cA[r * 36 + kk + qc]);
                a[mt][1] = tf32cvt(cA[(r + 8) * 36 + kk + qc]);
                a[mt][2] = tf32cvt(cA[r * 36 + kk + qc + 4]);
                a[mt][3] = tf32cvt(cA[(r + 8) * 36 + kk + qc + 4]);
            }
            #pragma unroll
            for (int nt = 0; nt < 8; nt++) {
                int cn = wc * 64 + nt * 8 + qr;
                bf[nt][0] = tf32cvt(cB[(kk + qc) * 132 + cn]);
                bf[nt][1] = tf32cvt(cB[(kk + qc + 4) * 132 + cn]);
            }
            #pragma unroll
            for (int mt = 0; mt < 2; mt++)
                #pragma unroll
                for (int nt = 0; nt < 8; nt++)
                    mma8(acc[mt][nt], a[mt], bf[nt]);
        }
        __syncthreads();
    }

    #pragma unroll
    for (int mt = 0; mt < 2; mt++) {
        int r = m0 + wr * 32 + mt * 16 + qr;
        #pragma unroll
        for (int nt = 0; nt < 8; nt++) {
            int col = n0 + wc * 64 + nt * 8 + qc * 2;
            *(float2*)(C + (size_t)r * Nd + col) =
                make_float2(acc[mt][nt][0] * alpha, acc[mt][nt][1] * alpha);
            *(float2*)(C + (size_t)(r + 8) * Nd + col) =
                make_float2(acc[mt][nt][2] * alpha, acc[mt][nt][3] * alpha);
        }
    }
}

// ---------------- bd GEMM: bd[bh][i][i+d] = (q_i + xlv_h) . R[511+d] ----------------
// grid (17, 4, 32), 256 threads, pipelined BK=32 over K_=128
#define BD_SMEM ((2 * 128 * 36 * 2 + 128) * 4)
__global__ void __launch_bounds__(256) bd_mma(const float* __restrict__ xlv)
{
    extern __shared__ float smf[];
    float* sA = smf;                      // 2 x [128][36]  (q rows)
    float* sB = smf + 2 * 128 * 36;       // 2 x [128][36]  (R rows, [n][k])
    float* xs = sB + 2 * 128 * 36;        // [128]
    unsigned sAa = saddr(sA), sBa = saddr(sB);

    int tid = threadIdx.x;
    int lane = tid & 31, wid = tid >> 5;
    int wr = wid >> 1, wc = wid & 1;
    int qr = lane >> 2, qc = lane & 3;
    int d0 = blockIdx.x * 128;
    int i0 = blockIdx.y * 128;
    int bh = blockIdx.z;
    int b = bh >> 3, h = bh & 7;

    for (int i = tid; i < 32; i += 256)
        *(float4*)&xs[i * 4] = *(const float4*)(xlv + h * K_ + i * 4);

    float acc[2][8][4];
    #pragma unroll
    for (int i = 0; i < 2; i++)
        #pragma unroll
        for (int j = 0; j < 8; j++)
            #pragma unroll
            for (int l = 0; l < 4; l++) acc[i][j][l] = 0.f;

    auto load_tiles = [&](int st, int k0) {
        unsigned da = sAa + st * (128 * 36 * 4);
        unsigned db = sBa + st * (128 * 36 * 4);
        #pragma unroll
        for (int j = 0; j < 4; j++) {
            int id = tid + j * 256;
            int r = id >> 3, c = (id & 7) << 2;
            cp16(da + (r * 36 + c) * 4,
                 g_q + (size_t)(b * L_ + i0 + r) * D_ + h * K_ + k0 + c);
            int rr = 511 + d0 + r; if (rr > W_ - 1) rr = W_ - 1;
            cp16(db + (r * 36 + c) * 4,
                 g_r + (size_t)rr * D_ + h * K_ + k0 + c);
        }
    };

    load_tiles(0, 0); cp_commit();

    for (int it = 0; it < 4; it++) {
        int st = it & 1;
        if (it + 1 < 4) { load_tiles(st ^ 1, (it + 1) << 5); cp_commit(); cp_wait1(); }
        else cp_wait0();
        __syncthreads();
        const float* cA = sA + st * (128 * 36);
        const float* cB = sB + st * (128 * 36);
        int k0 = it << 5;
        #pragma unroll
        for (int ks = 0; ks < 4; ks++) {
            const int kk = ks * 8;
            float xv0 = xs[k0 + kk + qc];
            float xv4 = xs[k0 + kk + qc + 4];
            unsigned a[2][4], bf[8][2];
            #pragma unroll
            for (int mt = 0; mt < 2; mt++) {
                int r = wr * 32 + mt * 16 + qr;
                a[mt][0] = tf32cvt(cA[r * 36 + kk + qc] + xv0);
                a[mt][1] = tf32cvt(cA[(r + 8) * 36 + kk + qc] + xv0);
                a[mt][2] = tf32cvt(cA[r * 36 + kk + qc + 4] + xv4);
                a[mt][3] = tf32cvt(cA[(r + 8) * 36 + kk + qc + 4] + xv4);
            }
            #pragma unroll
            for (int nt = 0; nt < 8; nt++) {
                int cn = wc * 64 + nt * 8 + qr;
                bf[nt][0] = tf32cvt(cB[cn * 36 + kk + qc]);
                bf[nt][1] = tf32cvt(cB[cn * 36 + kk + qc + 4]);
            }
            #pragma unroll
            for (int mt = 0; mt < 2; mt++)
                #pragma unroll
                for (int nt = 0; nt < 8; nt++)
                    mma8(acc[mt][nt], a[mt], bf[nt]);
        }
        __syncthreads();
    }

    #pragma unroll
    for (int mt = 0; mt < 2; mt++) {
        int gi = i0 + wr * 32 + mt * 16 + qr;
        float* r0 = g_bd + ((size_t)(bh * L_ + gi)) * W_ + gi;
        float* r1 = g_bd + ((size_t)(bh * L_ + gi + 8)) * W_ + gi + 8;
        #pragma unroll
        for (int nt = 0; nt < 8; nt++) {
            int gd = d0 + wc * 64 + nt * 8 + qc * 2;
            if (gd <= 2048)     { r0[gd]     = acc[mt][nt][0]; r1[gd]     = acc[mt][nt][2]; }
            if (gd + 1 <= 2048) { r0[gd + 1] = acc[mt][nt][1]; r1[gd + 1] = acc[mt][nt][3]; }
        }
    }
}

// ---------------- banded flash attention, pipelined ----------------
// smem (floats/u32 units):
//  Qs(u32)[64*132]=8448 | Kf 2x[64*132]=16896 | Vf 2x[64*136]=17408
//  Bd 2x[64*68]=8704 | Ssm [64*68]=4352 | mrow/lrow/arow 3x64
#define ATT_SMEM ((8448 + 16896 + 17408 + 8704 + 4352 + 192) * 4)
__global__ void __launch_bounds__(256) attn_mma(
    const float* __restrict__ cacheK, const float* __restrict__ cacheV,
    const float* __restrict__ xlu, const int* __restrict__ posp)
{
    extern __shared__ unsigned smu[];
    unsigned* Qs = smu;
    float* Kf  = (float*)(smu + 8448);
    float* Vf  = Kf + 16896;
    float* Bd  = Vf + 17408;
    float* Ssm = Bd + 8704;
    float* mrow = Ssm + 4352;
    float* lrow = mrow + 64;
    float* arow = lrow + 64;
    unsigned Ka = saddr(Kf), Va = saddr(Vf), Ba = saddr(Bd);

    int tid = threadIdx.x;
    int lane = tid & 31, wid = tid >> 5;
    int wr = wid >> 1, wc = wid & 1;
    int qr = lane >> 2, qc = lane & 3;
    int bh = blockIdx.y;
    int b = bh >> 3, h = bh & 7;
    int i0 = blockIdx.x * 64;
    int inval = M_ - posp[0]; if (inval < 0) inval = 0;

    auto load_kv = [&](int kt, int st) {
        int j0 = i0 + kt * 64;
        unsigned kd = Ka + st * (64 * 132 * 4);
        unsigned vd = Va + st * (64 * 136 * 4);
        #pragma unroll
        for (int j = 0; j < 8; j++) {
            int id = tid + j * 256;
            int r = id >> 5, c = (id & 31) << 2;
            int jj = j0 + r;
            const float *kp, *vp;
            if (jj < M_) {
                size_t off = ((size_t)bh * M_ + jj) * K_ + c;
                kp = cacheK + off; vp = cacheV + off;
            } else {
                size_t off = ((size_t)(b * L_ + (jj - M_))) * D_ + h * K_ + c;
                kp = g_k + off; vp = g_v + off;
            }
            cp16(kd + (r * 132 + c) * 4, kp);
            cp16(vd + (r * 136 + c) * 4, vp);
        }
        unsigned bd = Ba + st * (64 * 68 * 4);
        const float* bdb = g_bd + ((size_t)(bh * L_ + i0)) * W_ + j0;
        #pragma unroll
        for (int j = 0; j < 4; j++) {
            int id = tid + j * 256;
            int r = id >> 4, c = (id & 15) << 2;
            cp16(bd + (r * 68 + c) * 4, bdb + (size_t)r * W_ + c);
        }
    };

    load_kv(0, 0); cp_commit();

    // Q tile (+ xl_u) -> tf32 smem
    const float* qbase = g_q + ((size_t)(b * L_ + i0)) * D_ + h * K_;
    #pragma unroll
    for (int l = 0; l < 8; l++) {
        int idx = tid + l * 256;
        int r = idx >> 5, c = (idx & 31) << 2;
        float4 qv = *(const float4*)(qbase + (size_t)r * D_ + c);
        float4 uv = *(const float4*)(xlu + h * K_ + c);
        *(uint4*)&Qs[r * 132 + c] = make_uint4(
            tf32cvt(qv.x + uv.x), tf32cvt(qv.y + uv.y),
            tf32cvt(qv.z + uv.z), tf32cvt(qv.w + uv.w));
    }
    if (tid < 64) { mrow[tid] = -1e30f; lrow[tid] = 0.f; }

    float oacc[8][4];
    #pragma unroll
    for (int i = 0; i < 8; i++)
        #pragma unroll
        for (int j = 0; j < 4; j++) oacc[i][j] = 0.f;

    int srow = tid >> 2, sg = tid & 3;

    for (int kt = 0; kt < 33; kt++) {
        int st = kt & 1;
        int j0 = i0 + kt * 64;
        if (kt + 1 < 33) { load_kv(kt + 1, st ^ 1); cp_commit(); cp_wait1(); }
        else cp_wait0();
        __syncthreads();

        const float* cK = Kf + st * (64 * 132);
        const float* cV = Vf + st * (64 * 136);
        const float* cB = Bd + st * (64 * 68);

        // phase A: S = (Q+u) K^T
        float s[4][4];
        #pragma unroll
        for (int i = 0; i < 4; i++)
            #pragma unroll
            for (int j = 0; j < 4; j++) s[i][j] = 0.f;
        int r = wr * 16 + qr;
        #pragma unroll
        for (int ks = 0; ks < 16; ks++) {
            const int kk = ks * 8;
            unsigned a[4], bf[4][2];
            a[0] = Qs[r * 132 + kk + qc];
            a[1] = Qs[(r + 8) * 132 + kk + qc];
            a[2] = Qs[r * 132 + kk + qc + 4];
            a[3] = Qs[(r + 8) * 132 + kk + qc + 4];
            #pragma unroll
            for (int nt = 0; nt < 4; nt++) {
                int n = wc * 32 + nt * 8 + qr;
                bf[nt][0] = tf32cvt(cK[n * 132 + kk + qc]);
                bf[nt][1] = tf32cvt(cK[n * 132 + kk + qc + 4]);
            }
            #pragma unroll
            for (int nt = 0; nt < 4; nt++) mma8(s[nt], a, bf[nt]);
        }
        // add bd (from smem) + mask, write S to smem
        {
            int gi0 = i0 + r, gi1 = gi0 + 8;
            #pragma unroll
            for (int nt = 0; nt < 4; nt++) {
                int cbase = wc * 32 + nt * 8 + qc * 2;
                #pragma unroll
                for (int e = 0; e < 2; e++) {
                    int cc = cbase + e;
                    int gj = j0 + cc;
                    int dd0 = gj - gi0, dd1 = gj - gi1;
                    float b0 = cB[r * 68 + cc];
                    float b1 = cB[(r + 8) * 68 + cc];
                    float v0 = (dd0 >= 0 && dd0 <= 2048 && gj >= inval) ? (s[nt][e] + b0) : -1e30f;
                    float v1 = (dd1 >= 0 && dd1 <= 2048 && gj >= inval) ? (s[nt][2 + e] + b1) : -1e30f;
                    Ssm[r * 68 + cc] = v0;
                    Ssm[(r + 8) * 68 + cc] = v1;
                }
            }
        }
        __syncthreads();

        // phase B: online softmax (4 lanes / row); P stored as tf32 bits
        {
            float* Sr = Ssm + srow * 68 + sg * 16;
            float mx = -1e30f;
            #pragma unroll
            for (int c2 = 0; c2 < 16; c2++) mx = fmaxf(mx, Sr[c2]);
            mx = fmaxf(mx, __shfl_xor_sync(0xffffffffu, mx, 1));
            mx = fmaxf(mx, __shfl_xor_sync(0xffffffffu, mx, 2));
            float mold = mrow[srow];
            float mnew = fmaxf(mold, mx);
            float sum = 0.f;
            #pragma unroll
            for (int c2 = 0; c2 < 16; c2++) {
                float p = __expf(Sr[c2] - mnew);
                ((unsigned*)Sr)[c2] = tf32cvt(p);
                sum += p;
            }
            sum += __shfl_xor_sync(0xffffffffu, sum, 1);
            sum += __shfl_xor_sync(0xffffffffu, sum, 2);
            if (sg == 0) {
                float alpha = __expf(mold - mnew);
                arow[srow] = alpha;
                lrow[srow] = lrow[srow] * alpha + sum;
                mrow[srow] = mnew;
            }
        }
        __syncthreads();

        // phase C: rescale + O += P @ V
        {
            float al0 = arow[r], al1 = arow[r + 8];
            #pragma unroll
            for (int nt = 0; nt < 8; nt++) {
                oacc[nt][0] *= al0; oacc[nt][1] *= al0;
                oacc[nt][2] *= al1; oacc[nt][3] *= al1;
            }
            const unsigned* Pu = (const unsigned*)Ssm;
            #pragma unroll
            for (int ks = 0; ks < 8; ks++) {
                const int kk = ks * 8;
                unsigned a[4], bf[8][2];
                a[0] = Pu[r * 68 + kk + qc];
                a[1] = Pu[(r + 8) * 68 + kk + qc];
                a[2] = Pu[r * 68 + kk + qc + 4];
                a[3] = Pu[(r + 8) * 68 + kk + qc + 4];
                #pragma unroll
                for (int nt = 0; nt < 8; nt++) {
                    int n = wc * 64 + nt * 8 + qr;
                    bf[nt][0] = tf32cvt(cV[(kk + qc) * 136 + n]);
                    bf[nt][1] = tf32cvt(cV[(kk + qc + 4) * 136 + n]);
                }
                #pragma unroll
                for (int nt = 0; nt < 8; nt++) mma8(oacc[nt], a, bf[nt]);
            }
        }
        __syncthreads();
    }

    // epilogue
    {
        int r = wr * 16 + qr;
        float inv0 = 1.0f / lrow[r];
        float inv1 = 1.0f / lrow[r + 8];
        float* o0 = g_wv + ((size_t)(b * L_ + i0 + r)) * D_ + h * K_;
        float* o1 = g_wv + ((size_t)(b * L_ + i0 + r + 8)) * D_ + h * K_;
        #pragma unroll
        for (int nt = 0; nt < 8; nt++) {
            int col = wc * 64 + nt * 8 + qc * 2;
            *(float2*)(o0 + col) = make_float2(oacc[nt][0] * inv0, oacc[nt][1] * inv0);
            *(float2*)(o1 + col) = make_float2(oacc[nt][2] * inv1, oacc[nt][3] * inv1);
        }
    }
}

// ---------------- launch ----------------
extern "C" void kernel_launch(void* const* d_in, const int* in_sizes, int n_in,
                              void* d_out, int out_size)
{
    const float* x      = (const float*)d_in[0];
    const int*   pos    = (const int*)  d_in[1];
    const float* cacheK = (const float*)d_in[2];
    const float* cacheV = (const float*)d_in[3];
    const float* g_rms  = (const float*)d_in[4];
    const float* Wq     = (const float*)d_in[5];
    const float* Wk     = (const float*)d_in[6];
    const float* Wv     = (const float*)d_in[7];
    const float* Wr     = (const float*)d_in[8];
    const float* xlu    = (const float*)d_in[9];
    const float* xlv    = (const float*)d_in[10];
    const float* Wo     = (const float*)d_in[11];
    float* out          = (float*)d_out;

    float *p_xt, *p_q, *p_k, *p_v, *p_sin, *p_r, *p_wv;
    cudaGetSymbolAddress((void**)&p_xt,  g_xt);
    cudaGetSymbolAddress((void**)&p_q,   g_q);
    cudaGetSymbolAddress((void**)&p_k,   g_k);
    cudaGetSymbolAddress((void**)&p_v,   g_v);
    cudaGetSymbolAddress((void**)&p_sin, g_sin);
    cudaGetSymbolAddress((void**)&p_r,   g_r);
    cudaGetSymbolAddress((void**)&p_wv,  g_wv);

    cudaFuncSetAttribute(gemm_nn,  cudaFuncAttributeMaxDynamicSharedMemorySize, GEMM_SMEM);
    cudaFuncSetAttribute(bd_mma,   cudaFuncAttributeMaxDynamicSharedMemorySize, BD_SMEM);
    cudaFuncSetAttribute(attn_mma, cudaFuncAttributeMaxDynamicSharedMemorySize, ATT_SMEM);

    const float inv_tau = 0.08838834764831845f; // 1/sqrt(128)

    // 1) RMSNorm
    rmsnorm_kernel<<<B_ * L_, 256>>>(x, g_rms, p_xt);

    // 2) fused Q/K/V projections
    gemm_nn<<<dim3(D_ / 128, (B_ * L_) / 128, 3), 256, GEMM_SMEM>>>(
        p_xt, Wq, Wk, Wv, p_q, p_k, p_v, D_, D_, inv_tau, 1.0f, 1.0f);

    // 3) positional keys R = sinusoid @ Wr (only rows >= 384 are ever used)
    sinusoid_kernel<<<W_ / 64, 256>>>();
    gemm_nn<<<dim3(D_ / 128, 17, 1), 256, GEMM_SMEM>>>(
        p_sin + (size_t)384 * D_, Wr, Wr, Wr,
        p_r + (size_t)384 * D_, p_r, p_r, D_, D_, 1.0f, 1.0f, 1.0f);

    // 4) bd scores
    bd_mma<<<dim3(17, 4, 32), 256, BD_SMEM>>>(xlv);

    // 5) banded flash attention
    attn_mma<<<dim3(L_ / 64, B_ * H_), 256, ATT_SMEM>>>(cacheK, cacheV, xlu, pos);

    // 6) output projection
    gemm_nn<<<dim3(D_ / 128, (B_ * L_) / 128, 1), 256, GEMM_SMEM>>>(
        p_wv, Wo, Wo, Wo, out, out, out, D_, D_, 1.0f, 1.0f, 1.0f);
}